// round 3
// baseline (speedup 1.0000x reference)
#include <cuda_runtime.h>

#define BATCH 4
#define SEQ 2048
#define DMODEL 1024
#define NHEAD 16
#define DHEAD 64
#define MTOT (BATCH * SEQ)   // 8192

// Scratch (static device arrays: allowed; no runtime allocation)
__device__ float g_Q[MTOT * DMODEL];
__device__ float g_K[MTOT * DMODEL];
__device__ float g_V[MTOT * DMODEL];
__device__ float g_Y[MTOT * DMODEL];

// ---------------------------------------------------------------------------
// C[M,N] = A[M,K] * B[N,K]^T   (i.e. torch Linear: X @ W.T)
// 128x128 tile, BK=8, 256 threads, 8x8 per-thread register tile.
// Software-pipelined: global loads for tile k+1 are issued before the compute
// on tile k, hiding GMEM latency under the 512-FFMA block.
// ---------------------------------------------------------------------------
__global__ __launch_bounds__(256, 2) void sgemm_abt(
    const float* __restrict__ A, const float* __restrict__ Bw,
    float* __restrict__ C, int M, int N, int K)
{
    constexpr int BM = 128, BN = 128, BK = 8;
    __shared__ float As[BK][BM];
    __shared__ float Bs[BK][BN];

    const int tid = threadIdx.x;
    const int m0 = blockIdx.y * BM;
    const int n0 = blockIdx.x * BN;

    const int loadRow = tid >> 1;        // 0..127
    const int loadK   = (tid & 1) << 2;  // 0 or 4
    const int tr = tid >> 4;             // 0..15
    const int tc = tid & 15;             // 0..15

    const float* Ap = A  + (size_t)(m0 + loadRow) * K + loadK;
    const float* Bp = Bw + (size_t)(n0 + loadRow) * K + loadK;

    float acc[8][8] = {};

    // Prologue: load tile 0 into registers, stage to smem.
    float4 a = *(const float4*)(Ap);
    float4 b = *(const float4*)(Bp);

    for (int k0 = 0; k0 < K; k0 += BK) {
        As[loadK + 0][loadRow] = a.x;
        As[loadK + 1][loadRow] = a.y;
        As[loadK + 2][loadRow] = a.z;
        As[loadK + 3][loadRow] = a.w;
        Bs[loadK + 0][loadRow] = b.x;
        Bs[loadK + 1][loadRow] = b.y;
        Bs[loadK + 2][loadRow] = b.z;
        Bs[loadK + 3][loadRow] = b.w;
        __syncthreads();

        // Prefetch next tile while computing this one.
        if (k0 + BK < K) {
            a = *(const float4*)(Ap + k0 + BK);
            b = *(const float4*)(Bp + k0 + BK);
        }

#pragma unroll
        for (int kk = 0; kk < BK; kk++) {
            float ra[8], rb[8];
            *(float4*)&ra[0] = *(const float4*)&As[kk][tr * 8];
            *(float4*)&ra[4] = *(const float4*)&As[kk][tr * 8 + 4];
            *(float4*)&rb[0] = *(const float4*)&Bs[kk][tc * 8];
            *(float4*)&rb[4] = *(const float4*)&Bs[kk][tc * 8 + 4];
#pragma unroll
            for (int i = 0; i < 8; i++)
#pragma unroll
                for (int j = 0; j < 8; j++)
                    acc[i][j] += ra[i] * rb[j];
        }
        __syncthreads();
    }

#pragma unroll
    for (int i = 0; i < 8; i++) {
        float* Cp = C + (size_t)(m0 + tr * 8 + i) * N + n0 + tc * 8;
        *(float4*)Cp       = make_float4(acc[i][0], acc[i][1], acc[i][2], acc[i][3]);
        *(float4*)(Cp + 4) = make_float4(acc[i][4], acc[i][5], acc[i][6], acc[i][7]);
    }
}

// ---------------------------------------------------------------------------
// Flash attention, fp32. One CTA per (b, h, 64-row query tile).
// BQ = BKV = 64, DK = 64. 256 threads, 4x4 register tiles.
// Dynamic smem layout (stride 68 floats per 64-wide row to dodge conflicts):
//   QsT[64][68]  : Q tile transposed (d-major), pre-scaled by 1/sqrt(dk)
//   KPT[64][68]  : K tile transposed (d-major) — reused as P[row][key] buffer
//   Vs [64][68]  : V tile natural (key-major)
//   red[64][17]  : per-row partial reductions across the 16 column-threads
//   m_s/l_s/a_s[64] : running max / running sum / rescale factor
// ---------------------------------------------------------------------------
#define STRIDE 68
#define ATTN_SMEM_FLOATS (3 * 64 * STRIDE + 64 * 17 + 3 * 64)

__global__ __launch_bounds__(256) void attn_flash(
    const float* __restrict__ Q, const float* __restrict__ K,
    const float* __restrict__ V, float* __restrict__ Y)
{
    extern __shared__ float sm[];
    float* QsT = sm;
    float* KPT = QsT + 64 * STRIDE;
    float* Vs  = KPT + 64 * STRIDE;
    float* red = Vs  + 64 * STRIDE;
    float* m_s = red + 64 * 17;
    float* l_s = m_s + 64;
    float* a_s = l_s + 64;

    const int tid = threadIdx.x;
    const int qt = blockIdx.x;
    const int h  = blockIdx.y;
    const int b  = blockIdx.z;
    const float scale = 0.125f; // 1/sqrt(64)

    const size_t base = (size_t)b * SEQ * DMODEL + (size_t)h * DHEAD;

    const int lr = tid >> 4;          // 0..15
    const int lc = (tid & 15) << 2;   // 0,4,...,60
    const int tr = tid >> 4;          // row thread  (0..15)
    const int tc = tid & 15;          // col thread  (0..15)

    // Load + transpose + scale Q tile
#pragma unroll
    for (int rr = 0; rr < 4; rr++) {
        int r = lr + rr * 16;
        float4 q = *(const float4*)&Q[base + (size_t)(qt * 64 + r) * DMODEL + lc];
        QsT[(lc + 0) * STRIDE + r] = q.x * scale;
        QsT[(lc + 1) * STRIDE + r] = q.y * scale;
        QsT[(lc + 2) * STRIDE + r] = q.z * scale;
        QsT[(lc + 3) * STRIDE + r] = q.w * scale;
    }
    if (tid < 64) { m_s[tid] = -1e30f; l_s[tid] = 0.0f; }

    float o[4][4] = {};
    __syncthreads();

    for (int kt = 0; kt < SEQ / 64; kt++) {
        // Load K (transposed) and V (natural)
#pragma unroll
        for (int rr = 0; rr < 4; rr++) {
            int r = lr + rr * 16;
            float4 k4 = *(const float4*)&K[base + (size_t)(kt * 64 + r) * DMODEL + lc];
            KPT[(lc + 0) * STRIDE + r] = k4.x;
            KPT[(lc + 1) * STRIDE + r] = k4.y;
            KPT[(lc + 2) * STRIDE + r] = k4.z;
            KPT[(lc + 3) * STRIDE + r] = k4.w;
            float4 v4 = *(const float4*)&V[base + (size_t)(kt * 64 + r) * DMODEL + lc];
            *(float4*)&Vs[r * STRIDE + lc] = v4;
        }
        __syncthreads();

        // S = (Q*scale) @ K^T  — 4x4 per thread
        float s[4][4] = {};
#pragma unroll
        for (int d = 0; d < 64; d++) {
            float ra[4], rb[4];
            *(float4*)ra = *(const float4*)&QsT[d * STRIDE + tr * 4];
            *(float4*)rb = *(const float4*)&KPT[d * STRIDE + tc * 4];
#pragma unroll
            for (int i = 0; i < 4; i++)
#pragma unroll
                for (int j = 0; j < 4; j++)
                    s[i][j] += ra[i] * rb[j];
        }

        // Partial row maxima
#pragma unroll
        for (int i = 0; i < 4; i++) {
            float mx = fmaxf(fmaxf(s[i][0], s[i][1]), fmaxf(s[i][2], s[i][3]));
            red[(tr * 4 + i) * 17 + tc] = mx;
        }
        __syncthreads();

        if (tid < 64) {
            float mx = red[tid * 17];
#pragma unroll
            for (int k = 1; k < 16; k++) mx = fmaxf(mx, red[tid * 17 + k]);
            float mold = m_s[tid];
            float mnew = fmaxf(mold, mx);
            float a = __expf(mold - mnew);
            m_s[tid] = mnew;
            a_s[tid] = a;
            l_s[tid] *= a;
        }
        __syncthreads();

        // P = exp(S - m), store P[row][key] into KPT (K tile no longer needed),
        // partial row sums, rescale O accumulators.
#pragma unroll
        for (int i = 0; i < 4; i++) {
            int r = tr * 4 + i;
            float mrow = m_s[r];
            float p0 = __expf(s[i][0] - mrow);
            float p1 = __expf(s[i][1] - mrow);
            float p2 = __expf(s[i][2] - mrow);
            float p3 = __expf(s[i][3] - mrow);
            *(float4*)&KPT[r * STRIDE + tc * 4] = make_float4(p0, p1, p2, p3);
            red[r * 17 + tc] = p0 + p1 + p2 + p3;
            float a = a_s[r];
#pragma unroll
            for (int j = 0; j < 4; j++) o[i][j] *= a;
        }
        __syncthreads();

        if (tid < 64) {
            float rs = 0.0f;
#pragma unroll
            for (int k = 0; k < 16; k++) rs += red[tid * 17 + k];
            l_s[tid] += rs;
        }

        // O += P @ V
#pragma unroll
        for (int kk = 0; kk < 64; kk += 4) {
            float rp[4][4];
#pragma unroll
            for (int i = 0; i < 4; i++)
                *(float4*)rp[i] = *(const float4*)&KPT[(tr * 4 + i) * STRIDE + kk];
#pragma unroll
            for (int t = 0; t < 4; t++) {
                float rv[4];
                *(float4*)rv = *(const float4*)&Vs[(kk + t) * STRIDE + tc * 4];
#pragma unroll
                for (int i = 0; i < 4; i++)
#pragma unroll
                    for (int j = 0; j < 4; j++)
                        o[i][j] += rp[i][t] * rv[j];
            }
        }
        __syncthreads();
    }

    // Normalize and write out (same [B,T,D] head-sliced layout as inputs)
#pragma unroll
    for (int i = 0; i < 4; i++) {
        int r = tr * 4 + i;
        float inv = 1.0f / l_s[r];
        float4 w = make_float4(o[i][0] * inv, o[i][1] * inv,
                               o[i][2] * inv, o[i][3] * inv);
        *(float4*)&Y[base + (size_t)(qt * 64 + r) * DMODEL + tc * 4] = w;
    }
}

// ---------------------------------------------------------------------------
extern "C" void kernel_launch(void* const* d_in, const int* in_sizes, int n_in,
                              void* d_out, int out_size)
{
    const float* X  = (const float*)d_in[0];
    const float* Wq = (const float*)d_in[1];
    const float* Wk = (const float*)d_in[2];
    const float* Wv = (const float*)d_in[3];
    const float* Wo = (const float*)d_in[4];
    float* out = (float*)d_out;

    float *pQ, *pK, *pV, *pY;
    cudaGetSymbolAddress((void**)&pQ, g_Q);
    cudaGetSymbolAddress((void**)&pK, g_K);
    cudaGetSymbolAddress((void**)&pV, g_V);
    cudaGetSymbolAddress((void**)&pY, g_Y);

    cudaFuncSetAttribute(attn_flash, cudaFuncAttributeMaxDynamicSharedMemorySize,
                         ATTN_SMEM_FLOATS * 4);

    dim3 gGemm(DMODEL / 128, MTOT / 128);  // (8, 64)
    sgemm_abt<<<gGemm, 256>>>(X, Wq, pQ, MTOT, DMODEL, DMODEL);
    sgemm_abt<<<gGemm, 256>>>(X, Wk, pK, MTOT, DMODEL, DMODEL);
    sgemm_abt<<<gGemm, 256>>>(X, Wv, pV, MTOT, DMODEL, DMODEL);

    dim3 gAttn(SEQ / 64, NHEAD, BATCH);    // (32, 16, 4)
    attn_flash<<<gAttn, 256, ATTN_SMEM_FLOATS * 4>>>(pQ, pK, pV, pY);

    sgemm_abt<<<gGemm, 256>>>(pY, Wo, out, MTOT, DMODEL, DMODEL);
}

// round 4
// speedup vs baseline: 1.4783x; 1.4783x over previous
#include <cuda_runtime.h>
#include <cstdint>

#define BATCH 4
#define SEQ 2048
#define DMODEL 1024
#define NHEAD 16
#define DHEAD 64
#define MTOT (BATCH * SEQ)   // 8192

// Scratch (static device arrays: allowed; no runtime allocation)
__device__ float g_Q[MTOT * DMODEL];
__device__ float g_K[MTOT * DMODEL];
__device__ float g_V[MTOT * DMODEL];
__device__ float g_Y[MTOT * DMODEL];

// ---------------------------------------------------------------------------
// cp.async helpers
// ---------------------------------------------------------------------------
__device__ __forceinline__ void cp16(uint32_t dst_sh, const void* src) {
    asm volatile("cp.async.cg.shared.global [%0], [%1], 16;" :: "r"(dst_sh), "l"(src));
}
__device__ __forceinline__ void cp_commit() {
    asm volatile("cp.async.commit_group;");
}
template <int N>
__device__ __forceinline__ void cp_wait() {
    asm volatile("cp.async.wait_group %0;" :: "n"(N));
}
__device__ __forceinline__ uint32_t f2tf32(float x) {
    uint32_t u;
    asm("cvt.rna.tf32.f32 %0, %1;" : "=r"(u) : "f"(x));
    return u;
}
__device__ __forceinline__ void mma_tf32(float acc[4],
                                         const uint32_t a[4], const uint32_t b[2]) {
    asm volatile(
        "mma.sync.aligned.m16n8k8.row.col.f32.tf32.tf32.f32 "
        "{%0,%1,%2,%3}, {%4,%5,%6,%7}, {%8,%9}, {%0,%1,%2,%3};"
        : "+f"(acc[0]), "+f"(acc[1]), "+f"(acc[2]), "+f"(acc[3])
        : "r"(a[0]), "r"(a[1]), "r"(a[2]), "r"(a[3]), "r"(b[0]), "r"(b[1]));
}

// ---------------------------------------------------------------------------
// C[M,N] = A[M,K] * B[N,K]^T  in tf32 tensor cores, fp32 accumulate.
// 128x128x16 block tile, 8 warps (2x4), warp tile 64x32, m16n8k8 mma.
// cp.async double-buffered. Smem rows padded to 20 floats: fragment-read
// bank = (20*g + k) mod 32 hits all 32 banks -> conflict-free.
// ---------------------------------------------------------------------------
__global__ __launch_bounds__(256) void gemm_tf32_abt(
    const float* __restrict__ A, const float* __restrict__ Bw,
    float* __restrict__ C, int M, int N, int K)
{
    constexpr int BM = 128, BN = 128, BK = 16, PAD = 20;
    __shared__ float As[2][BM * PAD];
    __shared__ float Bs[2][BM * PAD];

    const int tid  = threadIdx.x;
    const int lane = tid & 31;
    const int warp = tid >> 5;
    const int warpM = warp >> 2;   // 0..1
    const int warpN = warp & 3;    // 0..3
    const int g  = lane >> 2;      // 0..7
    const int t4 = lane & 3;       // 0..3

    const int m0 = blockIdx.y * BM;
    const int n0 = blockIdx.x * BN;

    // Global->smem mapping: thread loads 2 float4 per tile (rows r, r+64)
    const int lrow = tid >> 2;     // 0..63
    const int lq   = tid & 3;      // which float4 in the 16-float row

    const float* Asrc0 = A  + (size_t)(m0 + lrow)      * K + lq * 4;
    const float* Asrc1 = A  + (size_t)(m0 + lrow + 64) * K + lq * 4;
    const float* Bsrc0 = Bw + (size_t)(n0 + lrow)      * K + lq * 4;
    const float* Bsrc1 = Bw + (size_t)(n0 + lrow + 64) * K + lq * 4;

    const int dst0 = lrow * PAD + lq * 4;
    const int dst1 = (lrow + 64) * PAD + lq * 4;

    uint32_t shA[2][2], shB[2][2];
    for (int s = 0; s < 2; s++) {
        shA[s][0] = (uint32_t)__cvta_generic_to_shared(&As[s][dst0]);
        shA[s][1] = (uint32_t)__cvta_generic_to_shared(&As[s][dst1]);
        shB[s][0] = (uint32_t)__cvta_generic_to_shared(&Bs[s][dst0]);
        shB[s][1] = (uint32_t)__cvta_generic_to_shared(&Bs[s][dst1]);
    }

    float acc[16][4] = {};   // [mf*4 + nf][c0..c3]

    // Prologue: stage 0
    cp16(shA[0][0], Asrc0); cp16(shA[0][1], Asrc1);
    cp16(shB[0][0], Bsrc0); cp16(shB[0][1], Bsrc1);
    cp_commit();

    const int NIT = K / BK;   // 64
    int stage = 0;

    const float* a_warp_base0 = &As[0][(warpM * 64) * PAD];
    const float* b_warp_base0 = &Bs[0][(warpN * 32) * PAD];
    const int stage_off = BM * PAD;

    for (int it = 0; it < NIT; it++) {
        if (it + 1 < NIT) {
            const int k = (it + 1) * BK;
            const int ns = stage ^ 1;
            cp16(shA[ns][0], Asrc0 + k); cp16(shA[ns][1], Asrc1 + k);
            cp16(shB[ns][0], Bsrc0 + k); cp16(shB[ns][1], Bsrc1 + k);
            cp_commit();
            cp_wait<1>();
        } else {
            cp_wait<0>();
        }
        __syncthreads();

        const float* ab = a_warp_base0 + stage * stage_off;
        const float* bb = b_warp_base0 + stage * stage_off;

#pragma unroll
        for (int ks = 0; ks < 2; ks++) {
            const int kb = ks * 8;
            uint32_t Ar[4][4], Br[4][2];
#pragma unroll
            for (int mf = 0; mf < 4; mf++) {
                const int r = mf * 16 + g;
                Ar[mf][0] = f2tf32(ab[r * PAD + kb + t4]);
                Ar[mf][1] = f2tf32(ab[(r + 8) * PAD + kb + t4]);
                Ar[mf][2] = f2tf32(ab[r * PAD + kb + t4 + 4]);
                Ar[mf][3] = f2tf32(ab[(r + 8) * PAD + kb + t4 + 4]);
            }
#pragma unroll
            for (int nf = 0; nf < 4; nf++) {
                const int c = nf * 8 + g;
                Br[nf][0] = f2tf32(bb[c * PAD + kb + t4]);
                Br[nf][1] = f2tf32(bb[c * PAD + kb + t4 + 4]);
            }
#pragma unroll
            for (int mf = 0; mf < 4; mf++)
#pragma unroll
                for (int nf = 0; nf < 4; nf++)
                    mma_tf32(acc[mf * 4 + nf], Ar[mf], Br[nf]);
        }
        __syncthreads();   // all reads done before next cp.async overwrites
        stage ^= 1;
    }

    // Epilogue: C frag layout c0=C[g][2t4], c1=C[g][2t4+1], c2/c3 at row+8
#pragma unroll
    for (int mf = 0; mf < 4; mf++) {
#pragma unroll
        for (int nf = 0; nf < 4; nf++) {
            const int idx = mf * 4 + nf;
            const int row = m0 + warpM * 64 + mf * 16 + g;
            const int col = n0 + warpN * 32 + nf * 8 + t4 * 2;
            *(float2*)&C[(size_t)row * N + col] =
                make_float2(acc[idx][0], acc[idx][1]);
            *(float2*)&C[(size_t)(row + 8) * N + col] =
                make_float2(acc[idx][2], acc[idx][3]);
        }
    }
}

// ---------------------------------------------------------------------------
// Flash attention, fp32. One CTA per (b, h, 64-row query tile).
// (unchanged from Round 0 — L1-bound; tensor-core rewrite is next round)
// ---------------------------------------------------------------------------
#define STRIDE 68
#define ATTN_SMEM_FLOATS (3 * 64 * STRIDE + 64 * 17 + 3 * 64)

__global__ __launch_bounds__(256) void attn_flash(
    const float* __restrict__ Q, const float* __restrict__ K,
    const float* __restrict__ V, float* __restrict__ Y)
{
    extern __shared__ float sm[];
    float* QsT = sm;
    float* KPT = QsT + 64 * STRIDE;
    float* Vs  = KPT + 64 * STRIDE;
    float* red = Vs  + 64 * STRIDE;
    float* m_s = red + 64 * 17;
    float* l_s = m_s + 64;
    float* a_s = l_s + 64;

    const int tid = threadIdx.x;
    const int qt = blockIdx.x;
    const int h  = blockIdx.y;
    const int b  = blockIdx.z;
    const float scale = 0.125f; // 1/sqrt(64)

    const size_t base = (size_t)b * SEQ * DMODEL + (size_t)h * DHEAD;

    const int lr = tid >> 4;
    const int lc = (tid & 15) << 2;
    const int tr = tid >> 4;
    const int tc = tid & 15;

#pragma unroll
    for (int rr = 0; rr < 4; rr++) {
        int r = lr + rr * 16;
        float4 q = *(const float4*)&Q[base + (size_t)(qt * 64 + r) * DMODEL + lc];
        QsT[(lc + 0) * STRIDE + r] = q.x * scale;
        QsT[(lc + 1) * STRIDE + r] = q.y * scale;
        QsT[(lc + 2) * STRIDE + r] = q.z * scale;
        QsT[(lc + 3) * STRIDE + r] = q.w * scale;
    }
    if (tid < 64) { m_s[tid] = -1e30f; l_s[tid] = 0.0f; }

    float o[4][4] = {};
    __syncthreads();

    for (int kt = 0; kt < SEQ / 64; kt++) {
#pragma unroll
        for (int rr = 0; rr < 4; rr++) {
            int r = lr + rr * 16;
            float4 k4 = *(const float4*)&K[base + (size_t)(kt * 64 + r) * DMODEL + lc];
            KPT[(lc + 0) * STRIDE + r] = k4.x;
            KPT[(lc + 1) * STRIDE + r] = k4.y;
            KPT[(lc + 2) * STRIDE + r] = k4.z;
            KPT[(lc + 3) * STRIDE + r] = k4.w;
            float4 v4 = *(const float4*)&V[base + (size_t)(kt * 64 + r) * DMODEL + lc];
            *(float4*)&Vs[r * STRIDE + lc] = v4;
        }
        __syncthreads();

        float s[4][4] = {};
#pragma unroll
        for (int d = 0; d < 64; d++) {
            float ra[4], rb[4];
            *(float4*)ra = *(const float4*)&QsT[d * STRIDE + tr * 4];
            *(float4*)rb = *(const float4*)&KPT[d * STRIDE + tc * 4];
#pragma unroll
            for (int i = 0; i < 4; i++)
#pragma unroll
                for (int j = 0; j < 4; j++)
                    s[i][j] += ra[i] * rb[j];
        }

#pragma unroll
        for (int i = 0; i < 4; i++) {
            float mx = fmaxf(fmaxf(s[i][0], s[i][1]), fmaxf(s[i][2], s[i][3]));
            red[(tr * 4 + i) * 17 + tc] = mx;
        }
        __syncthreads();

        if (tid < 64) {
            float mx = red[tid * 17];
#pragma unroll
            for (int k = 1; k < 16; k++) mx = fmaxf(mx, red[tid * 17 + k]);
            float mold = m_s[tid];
            float mnew = fmaxf(mold, mx);
            float a = __expf(mold - mnew);
            m_s[tid] = mnew;
            a_s[tid] = a;
            l_s[tid] *= a;
        }
        __syncthreads();

#pragma unroll
        for (int i = 0; i < 4; i++) {
            int r = tr * 4 + i;
            float mrow = m_s[r];
            float p0 = __expf(s[i][0] - mrow);
            float p1 = __expf(s[i][1] - mrow);
            float p2 = __expf(s[i][2] - mrow);
            float p3 = __expf(s[i][3] - mrow);
            *(float4*)&KPT[r * STRIDE + tc * 4] = make_float4(p0, p1, p2, p3);
            red[r * 17 + tc] = p0 + p1 + p2 + p3;
            float a = a_s[r];
#pragma unroll
            for (int j = 0; j < 4; j++) o[i][j] *= a;
        }
        __syncthreads();

        if (tid < 64) {
            float rs = 0.0f;
#pragma unroll
            for (int k = 0; k < 16; k++) rs += red[tid * 17 + k];
            l_s[tid] += rs;
        }

#pragma unroll
        for (int kk = 0; kk < 64; kk += 4) {
            float rp[4][4];
#pragma unroll
            for (int i = 0; i < 4; i++)
                *(float4*)rp[i] = *(const float4*)&KPT[(tr * 4 + i) * STRIDE + kk];
#pragma unroll
            for (int t = 0; t < 4; t++) {
                float rv[4];
                *(float4*)rv = *(const float4*)&Vs[(kk + t) * STRIDE + tc * 4];
#pragma unroll
                for (int i = 0; i < 4; i++)
#pragma unroll
                    for (int j = 0; j < 4; j++)
                        o[i][j] += rp[i][t] * rv[j];
            }
        }
        __syncthreads();
    }

#pragma unroll
    for (int i = 0; i < 4; i++) {
        int r = tr * 4 + i;
        float inv = 1.0f / l_s[r];
        float4 w = make_float4(o[i][0] * inv, o[i][1] * inv,
                               o[i][2] * inv, o[i][3] * inv);
        *(float4*)&Y[base + (size_t)(qt * 64 + r) * DMODEL + tc * 4] = w;
    }
}

// ---------------------------------------------------------------------------
extern "C" void kernel_launch(void* const* d_in, const int* in_sizes, int n_in,
                              void* d_out, int out_size)
{
    const float* X  = (const float*)d_in[0];
    const float* Wq = (const float*)d_in[1];
    const float* Wk = (const float*)d_in[2];
    const float* Wv = (const float*)d_in[3];
    const float* Wo = (const float*)d_in[4];
    float* out = (float*)d_out;

    float *pQ, *pK, *pV, *pY;
    cudaGetSymbolAddress((void**)&pQ, g_Q);
    cudaGetSymbolAddress((void**)&pK, g_K);
    cudaGetSymbolAddress((void**)&pV, g_V);
    cudaGetSymbolAddress((void**)&pY, g_Y);

    cudaFuncSetAttribute(attn_flash, cudaFuncAttributeMaxDynamicSharedMemorySize,
                         ATTN_SMEM_FLOATS * 4);

    dim3 gGemm(DMODEL / 128, MTOT / 128);  // (8, 64)
    gemm_tf32_abt<<<gGemm, 256>>>(X, Wq, pQ, MTOT, DMODEL, DMODEL);
    gemm_tf32_abt<<<gGemm, 256>>>(X, Wk, pK, MTOT, DMODEL, DMODEL);
    gemm_tf32_abt<<<gGemm, 256>>>(X, Wv, pV, MTOT, DMODEL, DMODEL);

    dim3 gAttn(SEQ / 64, NHEAD, BATCH);    // (32, 16, 4)
    attn_flash<<<gAttn, 256, ATTN_SMEM_FLOATS * 4>>>(pQ, pK, pV, pY);

    gemm_tf32_abt<<<gGemm, 256>>>(pY, Wo, out, MTOT, DMODEL, DMODEL);
}

// round 5
// speedup vs baseline: 2.6931x; 1.8218x over previous
#include <cuda_runtime.h>
#include <cstdint>

#define BATCH 4
#define SEQ 2048
#define DMODEL 1024
#define NHEAD 16
#define DHEAD 64
#define MTOT (BATCH * SEQ)   // 8192

// Scratch (static device arrays: allowed; no runtime allocation)
__device__ float g_Q[MTOT * DMODEL];
__device__ float g_K[MTOT * DMODEL];
__device__ float g_V[MTOT * DMODEL];
__device__ float g_Y[MTOT * DMODEL];

// ---------------------------------------------------------------------------
// helpers
// ---------------------------------------------------------------------------
__device__ __forceinline__ void cp16(uint32_t dst_sh, const void* src) {
    asm volatile("cp.async.cg.shared.global [%0], [%1], 16;" :: "r"(dst_sh), "l"(src));
}
__device__ __forceinline__ void cp_commit() {
    asm volatile("cp.async.commit_group;");
}
template <int N>
__device__ __forceinline__ void cp_wait() {
    asm volatile("cp.async.wait_group %0;" :: "n"(N));
}
__device__ __forceinline__ uint32_t f2tf32(float x) {
    uint32_t u;
    asm("cvt.rna.tf32.f32 %0, %1;" : "=r"(u) : "f"(x));
    return u;
}
__device__ __forceinline__ void mma_tf32(float acc[4],
                                         const uint32_t a[4], const uint32_t b[2]) {
    asm volatile(
        "mma.sync.aligned.m16n8k8.row.col.f32.tf32.tf32.f32 "
        "{%0,%1,%2,%3}, {%4,%5,%6,%7}, {%8,%9}, {%0,%1,%2,%3};"
        : "+f"(acc[0]), "+f"(acc[1]), "+f"(acc[2]), "+f"(acc[3])
        : "r"(a[0]), "r"(a[1]), "r"(a[2]), "r"(a[3]), "r"(b[0]), "r"(b[1]));
}

// ---------------------------------------------------------------------------
// C[M,N] = A[M,K] * B[N,K]^T  in tf32 tensor cores (unchanged from R4).
// ---------------------------------------------------------------------------
__global__ __launch_bounds__(256) void gemm_tf32_abt(
    const float* __restrict__ A, const float* __restrict__ Bw,
    float* __restrict__ C, int M, int N, int K)
{
    constexpr int BM = 128, BK = 16, PAD = 20;
    __shared__ float As[2][BM * PAD];
    __shared__ float Bs[2][BM * PAD];

    const int tid  = threadIdx.x;
    const int lane = tid & 31;
    const int warp = tid >> 5;
    const int warpM = warp >> 2;
    const int warpN = warp & 3;
    const int g  = lane >> 2;
    const int t4 = lane & 3;

    const int m0 = blockIdx.y * BM;
    const int n0 = blockIdx.x * 128;

    const int lrow = tid >> 2;
    const int lq   = tid & 3;

    const float* Asrc0 = A  + (size_t)(m0 + lrow)      * K + lq * 4;
    const float* Asrc1 = A  + (size_t)(m0 + lrow + 64) * K + lq * 4;
    const float* Bsrc0 = Bw + (size_t)(n0 + lrow)      * K + lq * 4;
    const float* Bsrc1 = Bw + (size_t)(n0 + lrow + 64) * K + lq * 4;

    const int dst0 = lrow * PAD + lq * 4;
    const int dst1 = (lrow + 64) * PAD + lq * 4;

    uint32_t shA[2][2], shB[2][2];
    for (int s = 0; s < 2; s++) {
        shA[s][0] = (uint32_t)__cvta_generic_to_shared(&As[s][dst0]);
        shA[s][1] = (uint32_t)__cvta_generic_to_shared(&As[s][dst1]);
        shB[s][0] = (uint32_t)__cvta_generic_to_shared(&Bs[s][dst0]);
        shB[s][1] = (uint32_t)__cvta_generic_to_shared(&Bs[s][dst1]);
    }

    float acc[16][4] = {};

    cp16(shA[0][0], Asrc0); cp16(shA[0][1], Asrc1);
    cp16(shB[0][0], Bsrc0); cp16(shB[0][1], Bsrc1);
    cp_commit();

    const int NIT = K / BK;
    int stage = 0;

    const float* a_warp_base0 = &As[0][(warpM * 64) * PAD];
    const float* b_warp_base0 = &Bs[0][(warpN * 32) * PAD];
    const int stage_off = BM * PAD;

    for (int it = 0; it < NIT; it++) {
        if (it + 1 < NIT) {
            const int k = (it + 1) * BK;
            const int ns = stage ^ 1;
            cp16(shA[ns][0], Asrc0 + k); cp16(shA[ns][1], Asrc1 + k);
            cp16(shB[ns][0], Bsrc0 + k); cp16(shB[ns][1], Bsrc1 + k);
            cp_commit();
            cp_wait<1>();
        } else {
            cp_wait<0>();
        }
        __syncthreads();

        const float* ab = a_warp_base0 + stage * stage_off;
        const float* bb = b_warp_base0 + stage * stage_off;

#pragma unroll
        for (int ks = 0; ks < 2; ks++) {
            const int kb = ks * 8;
            uint32_t Ar[4][4], Br[4][2];
#pragma unroll
            for (int mf = 0; mf < 4; mf++) {
                const int r = mf * 16 + g;
                Ar[mf][0] = f2tf32(ab[r * PAD + kb + t4]);
                Ar[mf][1] = f2tf32(ab[(r + 8) * PAD + kb + t4]);
                Ar[mf][2] = f2tf32(ab[r * PAD + kb + t4 + 4]);
                Ar[mf][3] = f2tf32(ab[(r + 8) * PAD + kb + t4 + 4]);
            }
#pragma unroll
            for (int nf = 0; nf < 4; nf++) {
                const int c = nf * 8 + g;
                Br[nf][0] = f2tf32(bb[c * PAD + kb + t4]);
                Br[nf][1] = f2tf32(bb[c * PAD + kb + t4 + 4]);
            }
#pragma unroll
            for (int mf = 0; mf < 4; mf++)
#pragma unroll
                for (int nf = 0; nf < 4; nf++)
                    mma_tf32(acc[mf * 4 + nf], Ar[mf], Br[nf]);
        }
        __syncthreads();
        stage ^= 1;
    }

#pragma unroll
    for (int mf = 0; mf < 4; mf++) {
#pragma unroll
        for (int nf = 0; nf < 4; nf++) {
            const int idx = mf * 4 + nf;
            const int row = m0 + warpM * 64 + mf * 16 + g;
            const int col = n0 + warpN * 32 + nf * 8 + t4 * 2;
            *(float2*)&C[(size_t)row * N + col] =
                make_float2(acc[idx][0], acc[idx][1]);
            *(float2*)&C[(size_t)(row + 8) * N + col] =
                make_float2(acc[idx][2], acc[idx][3]);
        }
    }
}

// ---------------------------------------------------------------------------
// Tensor-core flash attention (tf32 mma, fp32 accumulate).
// CTA: 128 Q-rows x one (b,h). 8 warps, each owns 16 Q-rows, all 64 dims/keys.
// Q fragments persist in registers; per-KV-tile: S mma -> in-register softmax
// -> P relayout via per-warp smem slice -> PV mma with online rescale.
// Smem strides: K/Q/P rows 68 floats (A/B frag reads conflict-free: bank=4g+t4),
// V rows 72 (B frag reads conflict-free: bank=8t4+g).
// ---------------------------------------------------------------------------
#define AKS 68
#define AVS 72
#define ATTN_SMEM_FLOATS (64 * AKS + 64 * AVS + 128 * AKS)

__global__ __launch_bounds__(256, 2) void attn_mma(
    const float* __restrict__ Q, const float* __restrict__ K,
    const float* __restrict__ V, float* __restrict__ Y)
{
    extern __shared__ float sm[];
    float* Ks = sm;                    // [64][68]
    float* Vs = Ks + 64 * AKS;         // [64][72]
    float* Ps = Vs + 64 * AVS;         // [128][68]  (also Q staging)

    const int tid  = threadIdx.x;
    const int lane = tid & 31;
    const int warp = tid >> 5;
    const int g  = lane >> 2;   // 0..7
    const int t4 = lane & 3;    // 0..3
    const int mrow = warp * 16;

    const int qt = blockIdx.x;
    const int h  = blockIdx.y;
    const int b  = blockIdx.z;
    const size_t base = (size_t)b * SEQ * DMODEL + (size_t)h * DHEAD;

    // ---- Stage Q tile (128x64, pre-scaled by 1/8) into Ps, then to frags ----
    {
        const int r = tid >> 1;
        const int c0 = (tid & 1) * 32;
        const float* src = &Q[base + (size_t)(qt * 128 + r) * DMODEL + c0];
#pragma unroll
        for (int i = 0; i < 8; i++) {
            float4 v = *(const float4*)(src + i * 4);
            Ps[r * AKS + c0 + i * 4 + 0] = v.x * 0.125f;
            Ps[r * AKS + c0 + i * 4 + 1] = v.y * 0.125f;
            Ps[r * AKS + c0 + i * 4 + 2] = v.z * 0.125f;
            Ps[r * AKS + c0 + i * 4 + 3] = v.w * 0.125f;
        }
    }
    __syncthreads();

    uint32_t qf[8][4];
#pragma unroll
    for (int kb = 0; kb < 8; kb++) {
        qf[kb][0] = f2tf32(Ps[(mrow + g) * AKS + kb * 8 + t4]);
        qf[kb][1] = f2tf32(Ps[(mrow + g + 8) * AKS + kb * 8 + t4]);
        qf[kb][2] = f2tf32(Ps[(mrow + g) * AKS + kb * 8 + t4 + 4]);
        qf[kb][3] = f2tf32(Ps[(mrow + g + 8) * AKS + kb * 8 + t4 + 4]);
    }
    __syncthreads();   // Ps free for reuse as P buffer

    float o[8][4] = {};
    float m0r = -1e30f, m1r = -1e30f;
    float l0 = 0.0f, l1 = 0.0f;

    const int lrow = tid >> 2;         // 0..63
    const int lq   = (tid & 3) * 16;   // 0,16,32,48

    for (int kt = 0; kt < SEQ / 64; kt++) {
        // ---- Load K,V tile (64x64) ----
        {
            const float* Kg = &K[base + (size_t)(kt * 64 + lrow) * DMODEL + lq];
            const float* Vg = &V[base + (size_t)(kt * 64 + lrow) * DMODEL + lq];
#pragma unroll
            for (int i = 0; i < 4; i++) {
                *(float4*)&Ks[lrow * AKS + lq + i * 4] = *(const float4*)(Kg + i * 4);
                *(float4*)&Vs[lrow * AVS + lq + i * 4] = *(const float4*)(Vg + i * 4);
            }
        }
        __syncthreads();

        // ---- S = Qs @ K^T  (16x64 per warp) ----
        float sacc[8][4] = {};
#pragma unroll
        for (int kb = 0; kb < 8; kb++) {
#pragma unroll
            for (int nf = 0; nf < 8; nf++) {
                uint32_t bf[2];
                bf[0] = f2tf32(Ks[(nf * 8 + g) * AKS + kb * 8 + t4]);
                bf[1] = f2tf32(Ks[(nf * 8 + g) * AKS + kb * 8 + t4 + 4]);
                mma_tf32(sacc[nf], qf[kb], bf);
            }
        }

        // ---- online softmax ----
        float rmax0 = -1e30f, rmax1 = -1e30f;
#pragma unroll
        for (int nf = 0; nf < 8; nf++) {
            rmax0 = fmaxf(rmax0, fmaxf(sacc[nf][0], sacc[nf][1]));
            rmax1 = fmaxf(rmax1, fmaxf(sacc[nf][2], sacc[nf][3]));
        }
        rmax0 = fmaxf(rmax0, __shfl_xor_sync(0xffffffffu, rmax0, 1));
        rmax0 = fmaxf(rmax0, __shfl_xor_sync(0xffffffffu, rmax0, 2));
        rmax1 = fmaxf(rmax1, __shfl_xor_sync(0xffffffffu, rmax1, 1));
        rmax1 = fmaxf(rmax1, __shfl_xor_sync(0xffffffffu, rmax1, 2));

        const float mnew0 = fmaxf(m0r, rmax0);
        const float mnew1 = fmaxf(m1r, rmax1);
        const float a0 = __expf(m0r - mnew0);
        const float a1 = __expf(m1r - mnew1);
        m0r = mnew0; m1r = mnew1;
        l0 *= a0;    l1 *= a1;

        float ps0 = 0.0f, ps1 = 0.0f;
#pragma unroll
        for (int nf = 0; nf < 8; nf++) {
            float p0 = __expf(sacc[nf][0] - m0r);
            float p1 = __expf(sacc[nf][1] - m0r);
            float p2 = __expf(sacc[nf][2] - m1r);
            float p3 = __expf(sacc[nf][3] - m1r);
            ps0 += p0 + p1;
            ps1 += p2 + p3;
            *(float2*)&Ps[(mrow + g) * AKS + nf * 8 + 2 * t4]     = make_float2(p0, p1);
            *(float2*)&Ps[(mrow + g + 8) * AKS + nf * 8 + 2 * t4] = make_float2(p2, p3);
            o[nf][0] *= a0; o[nf][1] *= a0;
            o[nf][2] *= a1; o[nf][3] *= a1;
        }
        l0 += ps0; l1 += ps1;
        __syncwarp();   // P visible to own warp (only own rows are read)

        // ---- O += P @ V ----
#pragma unroll
        for (int kk = 0; kk < 8; kk++) {
            uint32_t pf[4];
            pf[0] = f2tf32(Ps[(mrow + g) * AKS + kk * 8 + t4]);
            pf[1] = f2tf32(Ps[(mrow + g + 8) * AKS + kk * 8 + t4]);
            pf[2] = f2tf32(Ps[(mrow + g) * AKS + kk * 8 + t4 + 4]);
            pf[3] = f2tf32(Ps[(mrow + g + 8) * AKS + kk * 8 + t4 + 4]);
#pragma unroll
            for (int nf = 0; nf < 8; nf++) {
                uint32_t vf[2];
                vf[0] = f2tf32(Vs[(kk * 8 + t4) * AVS + nf * 8 + g]);
                vf[1] = f2tf32(Vs[(kk * 8 + t4 + 4) * AVS + nf * 8 + g]);
                mma_tf32(o[nf], pf, vf);
            }
        }
        __syncthreads();   // K/V reads done before next iter overwrites
    }

    // ---- finalize: reduce l across quad, normalize, write out ----
    l0 += __shfl_xor_sync(0xffffffffu, l0, 1);
    l0 += __shfl_xor_sync(0xffffffffu, l0, 2);
    l1 += __shfl_xor_sync(0xffffffffu, l1, 1);
    l1 += __shfl_xor_sync(0xffffffffu, l1, 2);
    const float inv0 = 1.0f / l0;
    const float inv1 = 1.0f / l1;

    const int row0 = qt * 128 + mrow + g;
#pragma unroll
    for (int nf = 0; nf < 8; nf++) {
        const int col = nf * 8 + 2 * t4;
        *(float2*)&Y[base + (size_t)row0 * DMODEL + col] =
            make_float2(o[nf][0] * inv0, o[nf][1] * inv0);
        *(float2*)&Y[base + (size_t)(row0 + 8) * DMODEL + col] =
            make_float2(o[nf][2] * inv1, o[nf][3] * inv1);
    }
}

// ---------------------------------------------------------------------------
extern "C" void kernel_launch(void* const* d_in, const int* in_sizes, int n_in,
                              void* d_out, int out_size)
{
    const float* X  = (const float*)d_in[0];
    const float* Wq = (const float*)d_in[1];
    const float* Wk = (const float*)d_in[2];
    const float* Wv = (const float*)d_in[3];
    const float* Wo = (const float*)d_in[4];
    float* out = (float*)d_out;

    float *pQ, *pK, *pV, *pY;
    cudaGetSymbolAddress((void**)&pQ, g_Q);
    cudaGetSymbolAddress((void**)&pK, g_K);
    cudaGetSymbolAddress((void**)&pV, g_V);
    cudaGetSymbolAddress((void**)&pY, g_Y);

    cudaFuncSetAttribute(attn_mma, cudaFuncAttributeMaxDynamicSharedMemorySize,
                         ATTN_SMEM_FLOATS * 4);

    dim3 gGemm(DMODEL / 128, MTOT / 128);  // (8, 64)
    gemm_tf32_abt<<<gGemm, 256>>>(X, Wq, pQ, MTOT, DMODEL, DMODEL);
    gemm_tf32_abt<<<gGemm, 256>>>(X, Wk, pK, MTOT, DMODEL, DMODEL);
    gemm_tf32_abt<<<gGemm, 256>>>(X, Wv, pV, MTOT, DMODEL, DMODEL);

    dim3 gAttn(SEQ / 128, NHEAD, BATCH);   // (16, 16, 4)
    attn_mma<<<gAttn, 256, ATTN_SMEM_FLOATS * 4>>>(pQ, pK, pV, pY);

    gemm_tf32_abt<<<gGemm, 256>>>(pY, Wo, out, MTOT, DMODEL, DMODEL);
}

// round 7
// speedup vs baseline: 3.0781x; 1.1429x over previous
#include <cuda_runtime.h>
#include <cstdint>

#define BATCH 4
#define SEQ 2048
#define DMODEL 1024
#define NHEAD 16
#define DHEAD 64
#define MTOT (BATCH * SEQ)   // 8192

// Scratch (static device arrays: allowed; no runtime allocation)
__device__ float g_Q[MTOT * DMODEL];
__device__ float g_K[MTOT * DMODEL];
__device__ float g_V[MTOT * DMODEL];
__device__ float g_Y[MTOT * DMODEL];

// ---------------------------------------------------------------------------
// helpers
// ---------------------------------------------------------------------------
__device__ __forceinline__ void cp16(uint32_t dst_sh, const void* src) {
    asm volatile("cp.async.cg.shared.global [%0], [%1], 16;" :: "r"(dst_sh), "l"(src));
}
__device__ __forceinline__ void cp_commit() {
    asm volatile("cp.async.commit_group;");
}
template <int N>
__device__ __forceinline__ void cp_wait() {
    asm volatile("cp.async.wait_group %0;" :: "n"(N));
}
__device__ __forceinline__ uint32_t f2tf32(float x) {
    uint32_t u;
    asm("cvt.rna.tf32.f32 %0, %1;" : "=r"(u) : "f"(x));
    return u;
}
__device__ __forceinline__ void mma_tf32(float acc[4],
                                         const uint32_t a[4], const uint32_t b[2]) {
    asm volatile(
        "mma.sync.aligned.m16n8k8.row.col.f32.tf32.tf32.f32 "
        "{%0,%1,%2,%3}, {%4,%5,%6,%7}, {%8,%9}, {%0,%1,%2,%3};"
        : "+f"(acc[0]), "+f"(acc[1]), "+f"(acc[2]), "+f"(acc[3])
        : "r"(a[0]), "r"(a[1]), "r"(a[2]), "r"(a[3]), "r"(b[0]), "r"(b[1]));
}

// ---------------------------------------------------------------------------
// tf32 GEMM mainloop body shared by the fused-QKV and single variants.
// C[M,N] = A[M,K] * B[N,K]^T. 128x128x16 tile, 8 warps, m16n8k8.
// ---------------------------------------------------------------------------
__device__ __forceinline__ void gemm_body(
    const float* __restrict__ A, const float* __restrict__ Bw,
    float* __restrict__ C, int M, int N, int K,
    int m0, int n0, float* As, float* Bs /* [2][128*PAD] each */)
{
    constexpr int BM = 128, BK = 16, PAD = 20;

    const int tid  = threadIdx.x;
    const int lane = tid & 31;
    const int warp = tid >> 5;
    const int warpM = warp >> 2;
    const int warpN = warp & 3;
    const int g  = lane >> 2;
    const int t4 = lane & 3;

    const int lrow = tid >> 2;
    const int lq   = tid & 3;

    const float* Asrc0 = A  + (size_t)(m0 + lrow)      * K + lq * 4;
    const float* Asrc1 = A  + (size_t)(m0 + lrow + 64) * K + lq * 4;
    const float* Bsrc0 = Bw + (size_t)(n0 + lrow)      * K + lq * 4;
    const float* Bsrc1 = Bw + (size_t)(n0 + lrow + 64) * K + lq * 4;

    const int dst0 = lrow * PAD + lq * 4;
    const int dst1 = (lrow + 64) * PAD + lq * 4;
    const int stage_off = BM * PAD;

    uint32_t shA[2][2], shB[2][2];
    for (int s = 0; s < 2; s++) {
        shA[s][0] = (uint32_t)__cvta_generic_to_shared(&As[s * stage_off + dst0]);
        shA[s][1] = (uint32_t)__cvta_generic_to_shared(&As[s * stage_off + dst1]);
        shB[s][0] = (uint32_t)__cvta_generic_to_shared(&Bs[s * stage_off + dst0]);
        shB[s][1] = (uint32_t)__cvta_generic_to_shared(&Bs[s * stage_off + dst1]);
    }

    float acc[16][4] = {};

    cp16(shA[0][0], Asrc0); cp16(shA[0][1], Asrc1);
    cp16(shB[0][0], Bsrc0); cp16(shB[0][1], Bsrc1);
    cp_commit();

    const int NIT = K / BK;
    int stage = 0;

    const float* a_warp_base0 = &As[(warpM * 64) * PAD];
    const float* b_warp_base0 = &Bs[(warpN * 32) * PAD];

    for (int it = 0; it < NIT; it++) {
        if (it + 1 < NIT) {
            const int k = (it + 1) * BK;
            const int ns = stage ^ 1;
            cp16(shA[ns][0], Asrc0 + k); cp16(shA[ns][1], Asrc1 + k);
            cp16(shB[ns][0], Bsrc0 + k); cp16(shB[ns][1], Bsrc1 + k);
            cp_commit();
            cp_wait<1>();
        } else {
            cp_wait<0>();
        }
        __syncthreads();

        const float* ab = a_warp_base0 + stage * stage_off;
        const float* bb = b_warp_base0 + stage * stage_off;

#pragma unroll
        for (int ks = 0; ks < 2; ks++) {
            const int kb = ks * 8;
            uint32_t Ar[4][4], Br[4][2];
#pragma unroll
            for (int mf = 0; mf < 4; mf++) {
                const int r = mf * 16 + g;
                Ar[mf][0] = f2tf32(ab[r * PAD + kb + t4]);
                Ar[mf][1] = f2tf32(ab[(r + 8) * PAD + kb + t4]);
                Ar[mf][2] = f2tf32(ab[r * PAD + kb + t4 + 4]);
                Ar[mf][3] = f2tf32(ab[(r + 8) * PAD + kb + t4 + 4]);
            }
#pragma unroll
            for (int nf = 0; nf < 4; nf++) {
                const int c = nf * 8 + g;
                Br[nf][0] = f2tf32(bb[c * PAD + kb + t4]);
                Br[nf][1] = f2tf32(bb[c * PAD + kb + t4 + 4]);
            }
#pragma unroll
            for (int mf = 0; mf < 4; mf++)
#pragma unroll
                for (int nf = 0; nf < 4; nf++)
                    mma_tf32(acc[mf * 4 + nf], Ar[mf], Br[nf]);
        }
        __syncthreads();
        stage ^= 1;
    }

#pragma unroll
    for (int mf = 0; mf < 4; mf++) {
#pragma unroll
        for (int nf = 0; nf < 4; nf++) {
            const int idx = mf * 4 + nf;
            const int row = m0 + warpM * 64 + mf * 16 + g;
            const int col = n0 + warpN * 32 + nf * 8 + t4 * 2;
            *(float2*)&C[(size_t)row * N + col] =
                make_float2(acc[idx][0], acc[idx][1]);
            *(float2*)&C[(size_t)(row + 8) * N + col] =
                make_float2(acc[idx][2], acc[idx][3]);
        }
    }
}

// Fused Q/K/V projections: blockIdx.z selects weight + destination.
__global__ __launch_bounds__(256) void gemm_tf32_qkv(
    const float* __restrict__ X,
    const float* __restrict__ Wq, const float* __restrict__ Wk,
    const float* __restrict__ Wv,
    float* __restrict__ Qo, float* __restrict__ Ko, float* __restrict__ Vo)
{
    __shared__ float As[2 * 128 * 20];
    __shared__ float Bs[2 * 128 * 20];
    const int z = blockIdx.z;
    const float* Bw = (z == 0) ? Wq : (z == 1) ? Wk : Wv;
    float* C = (z == 0) ? Qo : (z == 1) ? Ko : Vo;
    gemm_body(X, Bw, C, MTOT, DMODEL, DMODEL,
              blockIdx.y * 128, blockIdx.x * 128, As, Bs);
}

__global__ __launch_bounds__(256) void gemm_tf32_abt(
    const float* __restrict__ A, const float* __restrict__ Bw,
    float* __restrict__ C, int M, int N, int K)
{
    __shared__ float As[2 * 128 * 20];
    __shared__ float Bs[2 * 128 * 20];
    gemm_body(A, Bw, C, M, N, K, blockIdx.y * 128, blockIdx.x * 128, As, Bs);
}

// ---------------------------------------------------------------------------
// Tensor-core flash attention (tf32 mma, fp32 accumulate).
// CTA: 128 Q-rows x one (b,h). 8 warps, 16 Q-rows each.
// K and V are converted to tf32 ONCE at smem-store time (uint32 smem) —
// fragment reads are plain LDS, no per-read cvt.
// ---------------------------------------------------------------------------
#define AKS 68
#define AVS 72
#define ATTN_SMEM_FLOATS (64 * AKS + 64 * AVS + 128 * AKS)

__global__ __launch_bounds__(256, 2) void attn_mma(
    const float* __restrict__ Q, const float* __restrict__ K,
    const float* __restrict__ V, float* __restrict__ Y)
{
    extern __shared__ float sm[];
    uint32_t* Ksu = (uint32_t*)sm;             // [64][68] tf32
    uint32_t* Vsu = Ksu + 64 * AKS;            // [64][72] tf32
    float*    Ps  = (float*)(Vsu + 64 * AVS);  // [128][68] fp32 (Q staging / P)

    const int tid  = threadIdx.x;
    const int lane = tid & 31;
    const int warp = tid >> 5;
    const int g  = lane >> 2;   // 0..7
    const int t4 = lane & 3;    // 0..3
    const int mrow = warp * 16;

    const int qt = blockIdx.x;
    const int h  = blockIdx.y;
    const int b  = blockIdx.z;
    const size_t base = (size_t)b * SEQ * DMODEL + (size_t)h * DHEAD;

    // ---- Stage Q tile (128x64, pre-scaled by 1/8) into Ps, then to frags ----
    {
        const int r = tid >> 1;
        const int c0 = (tid & 1) * 32;
        const float* src = &Q[base + (size_t)(qt * 128 + r) * DMODEL + c0];
#pragma unroll
        for (int i = 0; i < 8; i++) {
            float4 v = *(const float4*)(src + i * 4);
            Ps[r * AKS + c0 + i * 4 + 0] = v.x * 0.125f;
            Ps[r * AKS + c0 + i * 4 + 1] = v.y * 0.125f;
            Ps[r * AKS + c0 + i * 4 + 2] = v.z * 0.125f;
            Ps[r * AKS + c0 + i * 4 + 3] = v.w * 0.125f;
        }
    }
    __syncthreads();

    uint32_t qf[8][4];
#pragma unroll
    for (int kb = 0; kb < 8; kb++) {
        qf[kb][0] = f2tf32(Ps[(mrow + g) * AKS + kb * 8 + t4]);
        qf[kb][1] = f2tf32(Ps[(mrow + g + 8) * AKS + kb * 8 + t4]);
        qf[kb][2] = f2tf32(Ps[(mrow + g) * AKS + kb * 8 + t4 + 4]);
        qf[kb][3] = f2tf32(Ps[(mrow + g + 8) * AKS + kb * 8 + t4 + 4]);
    }
    __syncthreads();   // Ps free for reuse as P buffer

    float o[8][4] = {};
    float m0r = -1e30f, m1r = -1e30f;
    float l0 = 0.0f, l1 = 0.0f;

    const int lrow = tid >> 2;         // 0..63
    const int lq   = (tid & 3) * 16;   // 0,16,32,48

    for (int kt = 0; kt < SEQ / 64; kt++) {
        // ---- Load K,V tile (64x64), converting to tf32 at store ----
        {
            const float* Kg = &K[base + (size_t)(kt * 64 + lrow) * DMODEL + lq];
            const float* Vg = &V[base + (size_t)(kt * 64 + lrow) * DMODEL + lq];
#pragma unroll
            for (int i = 0; i < 4; i++) {
                float4 kv = *(const float4*)(Kg + i * 4);
                float4 vv = *(const float4*)(Vg + i * 4);
                Ksu[lrow * AKS + lq + i * 4 + 0] = f2tf32(kv.x);
                Ksu[lrow * AKS + lq + i * 4 + 1] = f2tf32(kv.y);
                Ksu[lrow * AKS + lq + i * 4 + 2] = f2tf32(kv.z);
                Ksu[lrow * AKS + lq + i * 4 + 3] = f2tf32(kv.w);
                Vsu[lrow * AVS + lq + i * 4 + 0] = f2tf32(vv.x);
                Vsu[lrow * AVS + lq + i * 4 + 1] = f2tf32(vv.y);
                Vsu[lrow * AVS + lq + i * 4 + 2] = f2tf32(vv.z);
                Vsu[lrow * AVS + lq + i * 4 + 3] = f2tf32(vv.w);
            }
        }
        __syncthreads();

        // ---- S = Qs @ K^T  (16x64 per warp) ----
        float sacc[8][4] = {};
#pragma unroll
        for (int kb = 0; kb < 8; kb++) {
#pragma unroll
            for (int nf = 0; nf < 8; nf++) {
                uint32_t bf[2];
                bf[0] = Ksu[(nf * 8 + g) * AKS + kb * 8 + t4];
                bf[1] = Ksu[(nf * 8 + g) * AKS + kb * 8 + t4 + 4];
                mma_tf32(sacc[nf], qf[kb], bf);
            }
        }

        // ---- online softmax ----
        float rmax0 = -1e30f, rmax1 = -1e30f;
#pragma unroll
        for (int nf = 0; nf < 8; nf++) {
            rmax0 = fmaxf(rmax0, fmaxf(sacc[nf][0], sacc[nf][1]));
            rmax1 = fmaxf(rmax1, fmaxf(sacc[nf][2], sacc[nf][3]));
        }
        rmax0 = fmaxf(rmax0, __shfl_xor_sync(0xffffffffu, rmax0, 1));
        rmax0 = fmaxf(rmax0, __shfl_xor_sync(0xffffffffu, rmax0, 2));
        rmax1 = fmaxf(rmax1, __shfl_xor_sync(0xffffffffu, rmax1, 1));
        rmax1 = fmaxf(rmax1, __shfl_xor_sync(0xffffffffu, rmax1, 2));

        const float mnew0 = fmaxf(m0r, rmax0);
        const float mnew1 = fmaxf(m1r, rmax1);
        const float a0 = __expf(m0r - mnew0);
        const float a1 = __expf(m1r - mnew1);
        m0r = mnew0; m1r = mnew1;
        l0 *= a0;    l1 *= a1;

        float ps0 = 0.0f, ps1 = 0.0f;
#pragma unroll
        for (int nf = 0; nf < 8; nf++) {
            float p0 = __expf(sacc[nf][0] - m0r);
            float p1 = __expf(sacc[nf][1] - m0r);
            float p2 = __expf(sacc[nf][2] - m1r);
            float p3 = __expf(sacc[nf][3] - m1r);
            ps0 += p0 + p1;
            ps1 += p2 + p3;
            *(float2*)&Ps[(mrow + g) * AKS + nf * 8 + 2 * t4]     = make_float2(p0, p1);
            *(float2*)&Ps[(mrow + g + 8) * AKS + nf * 8 + 2 * t4] = make_float2(p2, p3);
            o[nf][0] *= a0; o[nf][1] *= a0;
            o[nf][2] *= a1; o[nf][3] *= a1;
        }
        l0 += ps0; l1 += ps1;
        __syncwarp();   // P visible to own warp (only own rows are read)

        // ---- O += P @ V ----
#pragma unroll
        for (int kk = 0; kk < 8; kk++) {
            uint32_t pf[4];
            pf[0] = f2tf32(Ps[(mrow + g) * AKS + kk * 8 + t4]);
            pf[1] = f2tf32(Ps[(mrow + g + 8) * AKS + kk * 8 + t4]);
            pf[2] = f2tf32(Ps[(mrow + g) * AKS + kk * 8 + t4 + 4]);
            pf[3] = f2tf32(Ps[(mrow + g + 8) * AKS + kk * 8 + t4 + 4]);
#pragma unroll
            for (int nf = 0; nf < 8; nf++) {
                uint32_t vf[2];
                vf[0] = Vsu[(kk * 8 + t4) * AVS + nf * 8 + g];
                vf[1] = Vsu[(kk * 8 + t4 + 4) * AVS + nf * 8 + g];
                mma_tf32(o[nf], pf, vf);
            }
        }
        __syncthreads();   // K/V reads done before next iter overwrites
    }

    // ---- finalize: reduce l across quad, normalize, write out ----
    l0 += __shfl_xor_sync(0xffffffffu, l0, 1);
    l0 += __shfl_xor_sync(0xffffffffu, l0, 2);
    l1 += __shfl_xor_sync(0xffffffffu, l1, 1);
    l1 += __shfl_xor_sync(0xffffffffu, l1, 2);
    const float inv0 = 1.0f / l0;
    const float inv1 = 1.0f / l1;

    const int row0 = qt * 128 + mrow + g;
#pragma unroll
    for (int nf = 0; nf < 8; nf++) {
        const int col = nf * 8 + 2 * t4;
        *(float2*)&Y[base + (size_t)row0 * DMODEL + col] =
            make_float2(o[nf][0] * inv0, o[nf][1] * inv0);
        *(float2*)&Y[base + (size_t)(row0 + 8) * DMODEL + col] =
            make_float2(o[nf][2] * inv1, o[nf][3] * inv1);
    }
}

// ---------------------------------------------------------------------------
extern "C" void kernel_launch(void* const* d_in, const int* in_sizes, int n_in,
                              void* d_out, int out_size)
{
    const float* X  = (const float*)d_in[0];
    const float* Wq = (const float*)d_in[1];
    const float* Wk = (const float*)d_in[2];
    const float* Wv = (const float*)d_in[3];
    const float* Wo = (const float*)d_in[4];
    float* out = (float*)d_out;

    float *pQ, *pK, *pV, *pY;
    cudaGetSymbolAddress((void**)&pQ, g_Q);
    cudaGetSymbolAddress((void**)&pK, g_K);
    cudaGetSymbolAddress((void**)&pV, g_V);
    cudaGetSymbolAddress((void**)&pY, g_Y);

    cudaFuncSetAttribute(attn_mma, cudaFuncAttributeMaxDynamicSharedMemorySize,
                         ATTN_SMEM_FLOATS * 4);

    dim3 gQKV(DMODEL / 128, MTOT / 128, 3);  // (8, 64, 3)
    gemm_tf32_qkv<<<gQKV, 256>>>(X, Wq, Wk, Wv, pQ, pK, pV);

    dim3 gAttn(SEQ / 128, NHEAD, BATCH);     // (16, 16, 4)
    attn_mma<<<gAttn, 256, ATTN_SMEM_FLOATS * 4>>>(pQ, pK, pV, pY);

    dim3 gGemm(DMODEL / 128, MTOT / 128);    // (8, 64)
    gemm_tf32_abt<<<gGemm, 256>>>(pY, Wo, out, MTOT, DMODEL, DMODEL);
}